// round 2
// baseline (speedup 1.0000x reference)
#include <cuda_runtime.h>
#include <cstdint>

#define N_NODES 50000
#define N_EDGES 400000
#define N_PATHS 512
#define DIM 64

// ---------------- device scratch (static: no runtime allocation) ----------------
__device__ float g_deg[N_NODES];                 // deg, then inverted in place
__device__ float g_agg[N_NODES * DIM];           // 12.8 MB
__device__ float g_h0[N_NODES * DIM];            // 12.8 MB
__device__ float g_h1[N_NODES * DIM];            // 12.8 MB
__device__ float g_edge[(size_t)N_EDGES * DIM];  // 102.4 MB
__device__ float g_path[N_PATHS * DIM];          // 128 KB
__device__ int   g_src[N_EDGES];
__device__ int   g_dst[N_EDGES];
__device__ int   g_is32;                         // dtype probe flag

// ---------------- index dtype probe + normalization ----------------
// If edge_index is int64 (values < 50000), every odd 32-bit word is 0.
// If it is int32, odd words are random node ids (all-zero prob ~ 0).
__global__ void probe_kernel(const int* __restrict__ ei_w, int* flag) {
    int i = blockIdx.x * blockDim.x + threadIdx.x;
    if (i == 0 && blockIdx.y == 0) { /* no-op */ }
    if (i < 4096) {
        if (ei_w[2 * i + 1] != 0) atomicOr(flag, 1);
    }
}

__global__ void zero_flag_kernel(int* flag) { *flag = 0; }

__global__ void cvt_idx_kernel(const void* __restrict__ ei,
                               const int* __restrict__ flag,
                               int* __restrict__ src, int* __restrict__ dst) {
    int e = blockIdx.x * blockDim.x + threadIdx.x;
    if (e >= N_EDGES) return;
    if (*flag) {  // int32 payload
        const int* p = (const int*)ei;
        src[e] = p[e];
        dst[e] = p[N_EDGES + e];
    } else {      // genuine int64 payload
        const long long* p = (const long long*)ei;
        src[e] = (int)p[e];
        dst[e] = (int)p[N_EDGES + e];
    }
}

// ---------------- small utility kernels ----------------
__global__ void zero_kernel(float* p, int n) {
    int i = blockIdx.x * blockDim.x + threadIdx.x;
    if (i < n) p[i] = 0.0f;
}

__global__ void deg_kernel(const int* __restrict__ dst, float* __restrict__ deg) {
    int e = blockIdx.x * blockDim.x + threadIdx.x;
    if (e < N_EDGES) atomicAdd(&deg[dst[e]], 1.0f);
}

__global__ void invdeg_kernel(float* __restrict__ deg) {
    int i = blockIdx.x * blockDim.x + threadIdx.x;
    if (i < N_NODES) deg[i] = 1.0f / fmaxf(deg[i], 1.0f);
}

// scatter-sum: agg[dst] += x[src], vectorized float4 atomics (sm_90+)
__global__ void scatter_kernel(const float* __restrict__ x,
                               const int* __restrict__ src,
                               const int* __restrict__ dst,
                               float* __restrict__ agg) {
    int idx = blockIdx.x * blockDim.x + threadIdx.x;
    if (idx >= N_EDGES * 16) return;
    int e = idx >> 4;
    int j = idx & 15;
    int s = src[e];
    int d = dst[e];
    float4 v = __ldg((const float4*)x + (size_t)s * 16 + j);
    atomicAdd((float4*)agg + (size_t)d * 16 + j, v);
}

// edge_emb[e] = (h[src] + h[dst]) * 0.5
__global__ void edge_emb_kernel(const float* __restrict__ h,
                                const int* __restrict__ src,
                                const int* __restrict__ dst,
                                float* __restrict__ eemb) {
    int idx = blockIdx.x * blockDim.x + threadIdx.x;
    if (idx >= N_EDGES * 16) return;
    int e = idx >> 4;
    int j = idx & 15;
    int s = src[e];
    int d = dst[e];
    float4 a = __ldg((const float4*)h + (size_t)s * 16 + j);
    float4 b = __ldg((const float4*)h + (size_t)d * 16 + j);
    float4 o;
    o.x = (a.x + b.x) * 0.5f;
    o.y = (a.y + b.y) * 0.5f;
    o.z = (a.z + b.z) * 0.5f;
    o.w = (a.w + b.w) * 0.5f;
    ((float4*)eemb)[(size_t)e * 16 + j] = o;
}

// ---------------- per-node SAGE linear: h = relu(agg*inv @ Wl + bl + x @ Wr) ----------------
#define SL_SMEM_FLOATS (4096 + 4096 + 64 * 68 + 64 * 68 + 64)
__global__ void __launch_bounds__(256) sage_linear_kernel(
    const float* __restrict__ agg, const float* __restrict__ inv,
    const float* __restrict__ x, const float* __restrict__ Wl,
    const float* __restrict__ Wr, const float* __restrict__ bl,
    float* __restrict__ h) {
    extern __shared__ float sm[];
    float* sWl = sm;                  // 64*64
    float* sWr = sWl + 4096;          // 64*64
    float* sA  = sWr + 4096;          // 64*68 (padded)
    float* sX  = sA + 64 * 68;        // 64*68
    float* sB  = sX + 64 * 68;        // 64

    int tid = threadIdx.x;
    for (int i = tid; i < 1024; i += 256) {
        ((float4*)sWl)[i] = ((const float4*)Wl)[i];
        ((float4*)sWr)[i] = ((const float4*)Wr)[i];
    }
    if (tid < 64) sB[tid] = bl[tid];

    int ntiles = (N_NODES + 63) / 64;
    for (int t = blockIdx.x; t < ntiles; t += gridDim.x) {
        int base = t * 64;
        __syncthreads();  // protect smem reuse across tiles
        for (int i = tid; i < 1024; i += 256) {
            int r = i >> 4;
            int c4 = i & 15;
            int row = base + r;
            float4 va = make_float4(0.f, 0.f, 0.f, 0.f);
            float4 vx = va;
            if (row < N_NODES) {
                va = ((const float4*)agg)[(size_t)row * 16 + c4];
                float iv = inv[row];
                va.x *= iv; va.y *= iv; va.z *= iv; va.w *= iv;
                vx = ((const float4*)x)[(size_t)row * 16 + c4];
            }
            *(float4*)&sA[r * 68 + c4 * 4] = va;
            *(float4*)&sX[r * 68 + c4 * 4] = vx;
        }
        __syncthreads();

        int r0 = (tid >> 4) * 4;
        int c0 = (tid & 15) * 4;
        float acc[4][4];
#pragma unroll
        for (int i = 0; i < 4; i++)
#pragma unroll
            for (int j = 0; j < 4; j++) acc[i][j] = sB[c0 + j];

#pragma unroll 8
        for (int k = 0; k < 64; k++) {
            float4 wl = *(const float4*)&sWl[k * 64 + c0];
            float4 wr = *(const float4*)&sWr[k * 64 + c0];
#pragma unroll
            for (int i = 0; i < 4; i++) {
                float a  = sA[(r0 + i) * 68 + k];
                float xv = sX[(r0 + i) * 68 + k];
                acc[i][0] += a * wl.x + xv * wr.x;
                acc[i][1] += a * wl.y + xv * wr.y;
                acc[i][2] += a * wl.z + xv * wr.z;
                acc[i][3] += a * wl.w + xv * wr.w;
            }
        }
#pragma unroll
        for (int i = 0; i < 4; i++) {
            int row = base + r0 + i;
            if (row < N_NODES) {
                float4 o;
                o.x = fmaxf(acc[i][0], 0.f);
                o.y = fmaxf(acc[i][1], 0.f);
                o.z = fmaxf(acc[i][2], 0.f);
                o.w = fmaxf(acc[i][3], 0.f);
                ((float4*)h)[(size_t)row * 16 + (c0 >> 2)] = o;
            }
        }
    }
}

// ---------------- big GEMM: path_emb[512,64] += path_masks[512,K] @ edge_emb[K,64] ----------------
// tf32 mma.sync m16n8k8, split-K across persistent CTAs, double-buffered cp.async
#define SA_STRIDE 36
#define SB_STRIDE 72
#define SA_FLOATS (512 * SA_STRIDE)                 // 18432
#define SB_FLOATS (32 * SB_STRIDE)                  // 2304
#define BUF_FLOATS (SA_FLOATS + SB_FLOATS)          // 20736
#define GEMM_SMEM_BYTES (2 * BUF_FLOATS * 4)        // 165888

__device__ __forceinline__ unsigned f2tf32(float f) {
    unsigned u;
    asm("cvt.rna.tf32.f32 %0, %1;" : "=r"(u) : "f"(f));
    return u;
}

__device__ __forceinline__ void mma8(float* c, const unsigned* a, unsigned b0, unsigned b1) {
    asm volatile(
        "mma.sync.aligned.m16n8k8.row.col.f32.tf32.tf32.f32 "
        "{%0,%1,%2,%3}, {%4,%5,%6,%7}, {%8,%9}, {%0,%1,%2,%3};"
        : "+f"(c[0]), "+f"(c[1]), "+f"(c[2]), "+f"(c[3])
        : "r"(a[0]), "r"(a[1]), "r"(a[2]), "r"(a[3]), "r"(b0), "r"(b1));
}

__device__ __forceinline__ void cp16(float* sdst, const float* gsrc) {
    unsigned s = (unsigned)__cvta_generic_to_shared(sdst);
    asm volatile("cp.async.cg.shared.global [%0], [%1], 16;" ::"r"(s), "l"(gsrc));
}

__device__ __forceinline__ void load_chunk(float* sA, float* sB,
                                           const float* __restrict__ A,
                                           const float* __restrict__ B,
                                           int k0, int tid) {
    // A chunk: 512 rows x 32 k = 4096 float4
#pragma unroll
    for (int i = 0; i < 8; i++) {
        int f = i * 512 + tid;
        int row = f >> 3;      // 8 float4 per row
        int c4 = f & 7;
        cp16(sA + row * SA_STRIDE + c4 * 4,
             A + (size_t)row * N_EDGES + k0 + c4 * 4);
    }
    // B chunk: 32 rows x 64 n = 512 float4
    {
        int row = tid >> 4;    // 16 float4 per row
        int c4 = tid & 15;
        cp16(sB + row * SB_STRIDE + c4 * 4,
             B + (size_t)(k0 + row) * 64 + c4 * 4);
    }
}

__global__ void __launch_bounds__(512, 1) path_gemm_kernel(
    const float* __restrict__ A, const float* __restrict__ B,
    float* __restrict__ C) {
    extern __shared__ float sm[];
    float* bA0 = sm;
    float* bB0 = sm + SA_FLOATS;
    float* bA1 = sm + BUF_FLOATS;
    float* bB1 = sm + BUF_FLOATS + SA_FLOATS;

    int tid = threadIdx.x;
    int lane = tid & 31;
    int warp = tid >> 5;
    int m0 = warp * 32;

    const int nch = N_EDGES / 32;  // 12500 (exact)
    int c0 = (int)(((long long)blockIdx.x * nch) / gridDim.x);
    int c1 = (int)(((long long)(blockIdx.x + 1) * nch) / gridDim.x);

    float acc[2][8][4] = {};

    load_chunk(bA0, bB0, A, B, c0 * 32, tid);
    asm volatile("cp.async.commit_group;");

    int buf = 0;
    for (int c = c0; c < c1; ++c) {
        float* cA = buf ? bA1 : bA0;
        float* cB = buf ? bB1 : bB0;
        float* nA = buf ? bA0 : bA1;
        float* nB = buf ? bB0 : bB1;
        if (c + 1 < c1) {
            load_chunk(nA, nB, A, B, (c + 1) * 32, tid);
            asm volatile("cp.async.commit_group;");
            asm volatile("cp.async.wait_group 1;");
        } else {
            asm volatile("cp.async.wait_group 0;");
        }
        __syncthreads();

#pragma unroll
        for (int kk = 0; kk < 32; kk += 8) {
            unsigned a[2][4];
            int rb = m0 + (lane >> 2);
            int kA = kk + (lane & 3);
#pragma unroll
            for (int mi = 0; mi < 2; mi++) {
                int r = rb + mi * 16;
                a[mi][0] = f2tf32(cA[r * SA_STRIDE + kA]);
                a[mi][1] = f2tf32(cA[(r + 8) * SA_STRIDE + kA]);
                a[mi][2] = f2tf32(cA[r * SA_STRIDE + kA + 4]);
                a[mi][3] = f2tf32(cA[(r + 8) * SA_STRIDE + kA + 4]);
            }
            int nb = lane >> 2;
#pragma unroll
            for (int ni = 0; ni < 8; ni++) {
                unsigned b0 = f2tf32(cB[kA * SB_STRIDE + ni * 8 + nb]);
                unsigned b1 = f2tf32(cB[(kA + 4) * SB_STRIDE + ni * 8 + nb]);
                mma8(acc[0][ni], a[0], b0, b1);
                mma8(acc[1][ni], a[1], b0, b1);
            }
        }
        __syncthreads();
        buf ^= 1;
    }

    // epilogue: accumulate C tile with vector L2 reductions
#pragma unroll
    for (int mi = 0; mi < 2; mi++) {
        int row = m0 + mi * 16 + (lane >> 2);
#pragma unroll
        for (int ni = 0; ni < 8; ni++) {
            int col = ni * 8 + 2 * (lane & 3);
            atomicAdd((float2*)&C[row * 64 + col],
                      make_float2(acc[mi][ni][0], acc[mi][ni][1]));
            atomicAdd((float2*)&C[(row + 8) * 64 + col],
                      make_float2(acc[mi][ni][2], acc[mi][ni][3]));
        }
    }
}

// ---------------- readout: out = path_emb @ Wro + bro ----------------
__global__ void readout_kernel(const float* __restrict__ P,
                               const float* __restrict__ W,
                               const float* __restrict__ b,
                               float* __restrict__ out) {
    int p = blockIdx.x;
    int d = threadIdx.x;
    float s = __ldg(&b[d]);
    const float* pr = P + p * 64;
#pragma unroll 16
    for (int k = 0; k < 64; k++) s += __ldg(&pr[k]) * __ldg(&W[k * 64 + d]);
    out[p * 64 + d] = s;
}

// ---------------- launcher ----------------
extern "C" void kernel_launch(void* const* d_in, const int* in_sizes, int n_in,
                              void* d_out, int out_size) {
    (void)in_sizes; (void)n_in; (void)out_size;
    const float* x        = (const float*)d_in[0];
    const void*  ei       = d_in[1];
    const float* pm       = (const float*)d_in[2];
    const float* Wl0      = (const float*)d_in[3];
    const float* Wr0      = (const float*)d_in[4];
    const float* bl0      = (const float*)d_in[5];
    const float* Wl1      = (const float*)d_in[6];
    const float* Wr1      = (const float*)d_in[7];
    const float* bl1      = (const float*)d_in[8];
    const float* Wro      = (const float*)d_in[9];
    const float* bro      = (const float*)d_in[10];
    float* out            = (float*)d_out;

    float *deg, *agg, *h0, *h1, *eemb, *pemb;
    int *src, *dst, *flag;
    cudaGetSymbolAddress((void**)&deg,  g_deg);
    cudaGetSymbolAddress((void**)&agg,  g_agg);
    cudaGetSymbolAddress((void**)&h0,   g_h0);
    cudaGetSymbolAddress((void**)&h1,   g_h1);
    cudaGetSymbolAddress((void**)&eemb, g_edge);
    cudaGetSymbolAddress((void**)&pemb, g_path);
    cudaGetSymbolAddress((void**)&src,  g_src);
    cudaGetSymbolAddress((void**)&dst,  g_dst);
    cudaGetSymbolAddress((void**)&flag, g_is32);

    cudaFuncSetAttribute(path_gemm_kernel,
                         cudaFuncAttributeMaxDynamicSharedMemorySize,
                         GEMM_SMEM_BYTES);
    cudaFuncSetAttribute(sage_linear_kernel,
                         cudaFuncAttributeMaxDynamicSharedMemorySize,
                         SL_SMEM_FLOATS * 4);

    // dtype probe + index normalization (int32 vs int64 edge_index)
    zero_flag_kernel<<<1, 1>>>(flag);
    probe_kernel<<<16, 256>>>((const int*)ei, flag);
    cvt_idx_kernel<<<(N_EDGES + 255) / 256, 256>>>(ei, flag, src, dst);

    // zero scratch
    zero_kernel<<<(N_NODES + 255) / 256, 256>>>(deg, N_NODES);
    zero_kernel<<<(N_NODES * DIM + 255) / 256, 256>>>(agg, N_NODES * DIM);
    zero_kernel<<<(N_PATHS * DIM + 255) / 256, 256>>>(pemb, N_PATHS * DIM);

    // degree + inverse
    deg_kernel<<<(N_EDGES + 255) / 256, 256>>>(dst, deg);
    invdeg_kernel<<<(N_NODES + 255) / 256, 256>>>(deg);

    // layer 0
    scatter_kernel<<<(N_EDGES * 16 + 255) / 256, 256>>>(x, src, dst, agg);
    sage_linear_kernel<<<296, 256, SL_SMEM_FLOATS * 4>>>(agg, deg, x, Wl0, Wr0, bl0, h0);

    // layer 1
    zero_kernel<<<(N_NODES * DIM + 255) / 256, 256>>>(agg, N_NODES * DIM);
    scatter_kernel<<<(N_EDGES * 16 + 255) / 256, 256>>>(h0, src, dst, agg);
    sage_linear_kernel<<<296, 256, SL_SMEM_FLOATS * 4>>>(agg, deg, h0, Wl1, Wr1, bl1, h1);

    // edge embeddings
    edge_emb_kernel<<<(N_EDGES * 16 + 255) / 256, 256>>>(h1, src, dst, eemb);

    // big split-K GEMM (tf32 tensor cores)
    path_gemm_kernel<<<148, 512, GEMM_SMEM_BYTES>>>(pm, eemb, pemb);

    // readout
    readout_kernel<<<N_PATHS, 64>>>(pemb, Wro, bro, out);
}